// round 6
// baseline (speedup 1.0000x reference)
#include <cuda_runtime.h>
#include <math.h>

#define NQ 6
#define NL 4
#define NA 4
#define PRE 64
#define NS 64

typedef unsigned long long u64;

__device__ __forceinline__ u64 pk(float lo_, float hi_) {
    u64 r; asm("mov.b64 %0, {%1, %2};" : "=l"(r) : "f"(lo_), "f"(hi_)); return r;
}
__device__ __forceinline__ void upk(u64 v, float &lo_, float &hi_) {
    asm("mov.b64 {%0, %1}, %2;" : "=f"(lo_), "=f"(hi_) : "l"(v));
}
__device__ __forceinline__ u64 fma2(u64 a, u64 b, u64 c) {
    u64 d; asm("fma.rn.f32x2 %0, %1, %2, %3;" : "=l"(d) : "l"(a), "l"(b), "l"(c)); return d;
}
__device__ __forceinline__ u64 mul2(u64 a, u64 b) {
    u64 d; asm("mul.rn.f32x2 %0, %1, %2;" : "=l"(d) : "l"(a), "l"(b)); return d;
}
__device__ __forceinline__ u64 add2(u64 a, u64 b) {
    u64 d; asm("add.rn.f32x2 %0, %1, %2;" : "=l"(d) : "l"(a), "l"(b)); return d;
}
__device__ __forceinline__ u64 relu2(u64 v) {
    float a, b; upk(v, a, b);
    return pk(fmaxf(a, 0.0f), fmaxf(b, 0.0f));
}
__device__ __forceinline__ u64 lds64(const float2* p) {
    return *reinterpret_cast<const u64*>(p);
}

__global__ void __launch_bounds__(128, 4) qpolicy_kernel(
    const float* __restrict__ x,
    const float* __restrict__ W1, const float* __restrict__ b1,
    const float* __restrict__ W2, const float* __restrict__ b2,
    const float* __restrict__ qw,
    const float* __restrict__ Wp, const float* __restrict__ bp,
    const float* __restrict__ Wv, const float* __restrict__ bv,
    float* __restrict__ out_policy, float* __restrict__ out_value,
    int NT)   // NT = B/2, two samples per thread in f32x2 lanes
{
    __shared__ __align__(16) float2 sW1d[PRE][8];   // [k][0..5]=W1 dup, [6]=b1 dup
    __shared__ __align__(16) float2 sW2d[PRE][6];   // [k][j]=W2[j][k] dup
    __shared__ __align__(16) float2 sb2d[NQ];
    __shared__ __align__(16) float2 sqTd[NL * NQ];  // ( t,  t)
    __shared__ __align__(16) float2 sqNd[NL * NQ];  // (-t, -t)
    __shared__ float scC[NL * NQ];
    __shared__ float scT[NL * NQ];
    __shared__ float sG2, sTc;
    __shared__ __align__(16) float2 sHead[NA + 1][8]; // [r][0..5]=2*G2*W, [7]=bias-G2*sumW*T

    const int tid = threadIdx.x;
    for (int i = tid; i < PRE * NQ; i += blockDim.x) {
        int k = i / NQ, q = i % NQ;
        float w = W1[i];
        sW1d[k][q] = make_float2(w, w);
        float w2 = W2[q * PRE + k];
        sW2d[k][q] = make_float2(w2, w2);
    }
    if (tid < PRE) { float v = b1[tid]; sW1d[tid][6] = make_float2(v, v); }
    if (tid < NQ)  { float v = b2[tid]; sb2d[tid] = make_float2(v, v); }
    if (tid < NL * NQ) {
        float s, c;
        sincosf(0.5f * qw[tid], &s, &c);
        float tt = s / c;
        scC[tid] = c;
        scT[tid] = tt;
        sqTd[tid] = make_float2(tt, tt);
        sqNd[tid] = make_float2(-tt, -tt);
    }
    __syncthreads();
    if (tid == 0) {
        float g = 1.0f, T = 1.0f;
#pragma unroll
        for (int i = 0; i < NL * NQ; ++i) {
            g *= scC[i];
            T *= 1.0f + scT[i] * scT[i];
        }
        sG2 = g * g;
        sTc = T;
    }
    __syncthreads();
    if (tid < NA + 1) {
        const float* Wr = (tid < NA) ? (Wp + tid * NQ) : Wv;
        float bias = (tid < NA) ? bp[tid] : bv[0];
        float g2 = sG2;
        float rs = 0.0f;
#pragma unroll
        for (int q = 0; q < NQ; ++q) rs += Wr[q];
#pragma unroll
        for (int q = 0; q < NQ; ++q) {
            float w = 2.0f * g2 * Wr[q];
            sHead[tid][q] = make_float2(w, w);
        }
        float bfull = bias + (-g2 * rs) * sTc;
        sHead[tid][7] = make_float2(bfull, bfull);
    }
    __syncthreads();

    const int t = blockIdx.x * blockDim.x + tid;
    if (t >= NT) return;

    // ---------------- load two samples --------------------------------------
    const float4* xr = reinterpret_cast<const float4*>(x + (size_t)t * 12);
    float4 v0 = xr[0], v1 = xr[1], v2 = xr[2];
    u64 XI[NQ];
    XI[0] = pk(v0.x, v1.z);
    XI[1] = pk(v0.y, v1.w);
    XI[2] = pk(v0.z, v2.x);
    XI[3] = pk(v0.w, v2.y);
    XI[4] = pk(v1.x, v2.z);
    XI[5] = pk(v1.y, v2.w);

    // ---------------- pre-net MLP (packed) ----------------------------------
    u64 acc[NQ];
#pragma unroll
    for (int j = 0; j < NQ; ++j) acc[j] = lds64(&sb2d[j]);

#pragma unroll
    for (int k = 0; k < PRE; ++k) {
        const ulonglong2* wq = reinterpret_cast<const ulonglong2*>(&sW1d[k][0]);
        u64 h = lds64(&sW1d[k][6]);
        ulonglong2 p01 = wq[0];
        h = fma2(p01.x, XI[0], h);
        h = fma2(p01.y, XI[1], h);
        ulonglong2 p23 = wq[1];
        h = fma2(p23.x, XI[2], h);
        h = fma2(p23.y, XI[3], h);
        ulonglong2 p45 = wq[2];
        h = fma2(p45.x, XI[4], h);
        h = fma2(p45.y, XI[5], h);
        h = relu2(h);
        const ulonglong2* w2 = reinterpret_cast<const ulonglong2*>(&sW2d[k][0]);
        ulonglong2 a01 = w2[0];
        acc[0] = fma2(a01.x, h, acc[0]);
        acc[1] = fma2(a01.y, h, acc[1]);
        ulonglong2 a23 = w2[1];
        acc[2] = fma2(a23.x, h, acc[2]);
        acc[3] = fma2(a23.y, h, acc[3]);
        ulonglong2 a45 = w2[2];
        acc[4] = fma2(a45.x, h, acc[4]);
        acc[5] = fma2(a45.y, h, acc[5]);
    }

    // ---------------- angle embedding ---------------------------------------
    u64 ECP[NQ], ESP[NQ];
#pragma unroll
    for (int j = 0; j < NQ; ++j) {
        float a0, a1;
        upk(relu2(acc[j]), a0, a1);
        float s0, c0, s1c, c1;
        __sincosf(0.5f * a0, &s0, &c0);
        __sincosf(0.5f * a1, &s1c, &c1);
        ECP[j] = pk(c0, c1);
        ESP[j] = pk(s0, s1c);
    }

    u64 P[NS];
    P[0] = ECP[0];
    P[1] = ESP[0];
#pragma unroll
    for (int q = 1; q < NQ; ++q) {
        const int sz = 1 << q;
#pragma unroll
        for (int i = 0; i < NS; ++i) {
            if (i < sz) {
                P[i | sz] = mul2(P[i], ESP[q]);
                P[i]      = mul2(P[i], ECP[q]);
            }
        }
    }

    // ---------------- 4 layers: CNOT renames + tan-form RY (2 fma2/bfly) ----
#pragma unroll
    for (int l = 0; l < NL; ++l) {
#pragma unroll
        for (int i = 0; i < NQ; ++i) {
            const int cb = 1 << i;
            const int tb = 1 << ((i + 1) % NQ);
#pragma unroll
            for (int idx = 0; idx < NS; ++idx) {
                if ((idx & cb) && !(idx & tb)) {
                    u64 tmp = P[idx];
                    P[idx] = P[idx | tb];
                    P[idx | tb] = tmp;
                }
            }
        }
#pragma unroll
        for (int i = 0; i < NQ; ++i) {
            const int g = l * NQ + i;
            const u64 Tt = lds64(&sqTd[g]);
            const u64 Nt = lds64(&sqNd[g]);
            const int qb = 1 << i;
#pragma unroll
            for (int base = 0; base < NS; ++base) {
                if (!(base & qb)) {
                    u64 A = P[base];
                    u64 B = P[base | qb];
                    P[base]      = fma2(Nt, B, A);
                    P[base | qb] = fma2(Tt, A, B);
                }
            }
        }
    }

    // ---------------- measurement (in place: P becomes probabilities) -------
#pragma unroll
    for (int i = 0; i < NS; ++i) P[i] = mul2(P[i], P[i]);

    u64 F[6];
    // level 1: pairs over bit0; E0 accumulates even entries
    {
        u64 e0a = pk(0.f, 0.f), e0b = pk(0.f, 0.f);
#pragma unroll
        for (int i = 0; i < 32; ++i) {
            u64 ev = P[2 * i], od = P[2 * i + 1];
            if (i & 1) e0b = add2(e0b, ev); else e0a = add2(e0a, ev);
            P[i] = add2(ev, od);    // compact into P[0..31]
        }
        F[0] = add2(e0a, e0b);
    }
    {
        u64 e1a = pk(0.f, 0.f), e1b = pk(0.f, 0.f);
#pragma unroll
        for (int i = 0; i < 16; ++i) {
            u64 ev = P[2 * i], od = P[2 * i + 1];
            if (i & 1) e1b = add2(e1b, ev); else e1a = add2(e1a, ev);
            P[i] = add2(ev, od);
        }
        F[1] = add2(e1a, e1b);
    }
    {
        u64 e2 = pk(0.f, 0.f);
#pragma unroll
        for (int i = 0; i < 8; ++i) {
            u64 ev = P[2 * i], od = P[2 * i + 1];
            e2 = add2(e2, ev);
            P[i] = add2(ev, od);
        }
        F[2] = e2;
    }
    {
        u64 e3 = pk(0.f, 0.f);
#pragma unroll
        for (int i = 0; i < 4; ++i) {
            u64 ev = P[2 * i], od = P[2 * i + 1];
            e3 = add2(e3, ev);
            P[i] = add2(ev, od);
        }
        F[3] = e3;
    }
    F[4] = add2(P[0], P[2]);
    F[5] = add2(P[0], P[1]);

    // ---------------- heads --------------------------------------------------
    u64 L[NA + 1];
#pragma unroll
    for (int r = 0; r < NA + 1; ++r) {
        u64 a = lds64(&sHead[r][7]);
#pragma unroll
        for (int q = 0; q < NQ; ++q)
            a = fma2(lds64(&sHead[r][q]), F[q], a);
        L[r] = a;
    }
    float l0[NA], l1[NA];
#pragma unroll
    for (int a = 0; a < NA; ++a) upk(L[a], l0[a], l1[a]);

    {
        float m = fmaxf(fmaxf(l0[0], l0[1]), fmaxf(l0[2], l0[3]));
        float e0 = __expf(l0[0] - m), e1 = __expf(l0[1] - m);
        float e2 = __expf(l0[2] - m), e3 = __expf(l0[3] - m);
        float inv = __fdividef(1.0f, e0 + e1 + e2 + e3);
        reinterpret_cast<float4*>(out_policy)[2 * t] =
            make_float4(e0 * inv, e1 * inv, e2 * inv, e3 * inv);
    }
    {
        float m = fmaxf(fmaxf(l1[0], l1[1]), fmaxf(l1[2], l1[3]));
        float e0 = __expf(l1[0] - m), e1 = __expf(l1[1] - m);
        float e2 = __expf(l1[2] - m), e3 = __expf(l1[3] - m);
        float inv = __fdividef(1.0f, e0 + e1 + e2 + e3);
        reinterpret_cast<float4*>(out_policy)[2 * t + 1] =
            make_float4(e0 * inv, e1 * inv, e2 * inv, e3 * inv);
    }

    float va, vb; upk(L[NA], va, vb);
    reinterpret_cast<float2*>(out_value)[t] = make_float2(va, vb);
}

extern "C" void kernel_launch(void* const* d_in, const int* in_sizes, int n_in,
                              void* d_out, int out_size) {
    const float* x  = (const float*)d_in[0];
    const float* W1 = (const float*)d_in[1];
    const float* b1 = (const float*)d_in[2];
    const float* W2 = (const float*)d_in[3];
    const float* b2 = (const float*)d_in[4];
    const float* qw = (const float*)d_in[5];
    const float* Wp = (const float*)d_in[6];
    const float* bp = (const float*)d_in[7];
    const float* Wv = (const float*)d_in[8];
    const float* bv = (const float*)d_in[9];

    const int B  = in_sizes[0] / NQ;
    const int NT = B / 2;
    float* out_policy = (float*)d_out;
    float* out_value  = (float*)d_out + (size_t)B * NA;

    const int threads = 128;
    const int blocks = (NT + threads - 1) / threads;
    qpolicy_kernel<<<blocks, threads>>>(x, W1, b1, W2, b2, qw, Wp, bp, Wv, bv,
                                        out_policy, out_value, NT);
}

// round 8
// speedup vs baseline: 1.4355x; 1.4355x over previous
#include <cuda_runtime.h>
#include <math.h>

#define NQ 6
#define NL 4
#define NA 4
#define PRE 64
#define NS 64

typedef unsigned long long u64;

// ---- gate + head constants (uniform across all samples) --------------------
struct QConst {
    u64 T[NL * NQ];       // ( t,  t) per gate
    u64 N[NL * NQ];       // (-t, -t) per gate
    u64 Hw[NA + 1][NQ];   // (2*G2*w, dup)
    u64 Hb[NA + 1];       // (bias - G2*sumW*Tc, dup)
};
__constant__ QConst cq;
__device__ QConst g_stage;

__device__ __forceinline__ u64 pk(float lo_, float hi_) {
    u64 r; asm("mov.b64 %0, {%1, %2};" : "=l"(r) : "f"(lo_), "f"(hi_)); return r;
}
__device__ __forceinline__ void upk(u64 v, float &lo_, float &hi_) {
    asm("mov.b64 {%0, %1}, %2;" : "=f"(lo_), "=f"(hi_) : "l"(v));
}
__device__ __forceinline__ u64 fma2(u64 a, u64 b, u64 c) {
    u64 d; asm("fma.rn.f32x2 %0, %1, %2, %3;" : "=l"(d) : "l"(a), "l"(b), "l"(c)); return d;
}
__device__ __forceinline__ u64 mul2(u64 a, u64 b) {
    u64 d; asm("mul.rn.f32x2 %0, %1, %2;" : "=l"(d) : "l"(a), "l"(b)); return d;
}
__device__ __forceinline__ u64 add2(u64 a, u64 b) {
    u64 d; asm("add.rn.f32x2 %0, %1, %2;" : "=l"(d) : "l"(a), "l"(b)); return d;
}
__device__ __forceinline__ u64 relu2(u64 v) {
    float a, b; upk(v, a, b);
    return pk(fmaxf(a, 0.0f), fmaxf(b, 0.0f));
}
__device__ __forceinline__ u64 lds64(const float2* p) {
    return *reinterpret_cast<const u64*>(p);
}

// ============================================================================
// Builder: tan-form gate constants + folded head weights -> staging buffer.
// ============================================================================
__global__ void build_consts(
    const float* __restrict__ qw,
    const float* __restrict__ Wp, const float* __restrict__ bp,
    const float* __restrict__ Wv, const float* __restrict__ bv)
{
    const int tid = threadIdx.x;   // 32 threads
    __shared__ float sc[NL * NQ], stt[NL * NQ];
    __shared__ float sG2, sTc;

    if (tid < NL * NQ) {
        float s, c;
        sincosf(0.5f * qw[tid], &s, &c);
        float t = s / c;
        sc[tid] = c;
        stt[tid] = t;
        g_stage.T[tid] = pk(t, t);
        g_stage.N[tid] = pk(-t, -t);
    }
    __syncthreads();
    if (tid == 0) {
        float g = 1.0f, T = 1.0f;
#pragma unroll
        for (int i = 0; i < NL * NQ; ++i) {
            g *= sc[i];
            T *= 1.0f + stt[i] * stt[i];
        }
        sG2 = g * g;
        sTc = T;
    }
    __syncthreads();
    if (tid < (NA + 1) * NQ) {
        int r = tid / NQ, q = tid % NQ;
        float w = (r < NA) ? Wp[r * NQ + q] : Wv[q];
        float v = 2.0f * sG2 * w;
        g_stage.Hw[r][q] = pk(v, v);
    }
    if (tid < NA + 1) {
        const float* Wr = (tid < NA) ? (Wp + tid * NQ) : Wv;
        float bias = (tid < NA) ? bp[tid] : bv[0];
        float rs = 0.0f;
#pragma unroll
        for (int q = 0; q < NQ; ++q) rs += Wr[q];
        float v = bias - sG2 * rs * sTc;
        g_stage.Hb[tid] = pk(v, v);
    }
}

// ============================================================================
// Main kernel: packed 2 samples/thread; gates read constants from cbank (UR).
// ============================================================================
__global__ void __launch_bounds__(128) qpolicy_kernel(
    const float* __restrict__ x,
    const float* __restrict__ W1, const float* __restrict__ b1,
    const float* __restrict__ W2, const float* __restrict__ b2,
    float* __restrict__ out_policy, float* __restrict__ out_value,
    int NT)   // NT = B/2
{
    __shared__ __align__(16) float2 sW1d[PRE][8];   // [k][0..5]=W1 dup, [6]=b1 dup
    __shared__ __align__(16) float2 sW2d[PRE][6];   // [k][j]=W2[j][k] dup
    __shared__ __align__(16) float2 sb2d[NQ];

    const int tid = threadIdx.x;
    for (int i = tid; i < PRE * NQ; i += blockDim.x) {
        int k = i / NQ, q = i % NQ;
        float w = W1[i];
        sW1d[k][q] = make_float2(w, w);
        float w2 = W2[q * PRE + k];
        sW2d[k][q] = make_float2(w2, w2);
    }
    if (tid < PRE) { float v = b1[tid]; sW1d[tid][6] = make_float2(v, v); }
    if (tid < NQ)  { float v = b2[tid]; sb2d[tid] = make_float2(v, v); }
    __syncthreads();

    const int t = blockIdx.x * blockDim.x + tid;
    if (t >= NT) return;

    // ---------------- load two samples --------------------------------------
    const float4* xr = reinterpret_cast<const float4*>(x + (size_t)t * 12);
    float4 v0 = xr[0], v1 = xr[1], v2 = xr[2];
    u64 XI[NQ];
    XI[0] = pk(v0.x, v1.z);
    XI[1] = pk(v0.y, v1.w);
    XI[2] = pk(v0.z, v2.x);
    XI[3] = pk(v0.w, v2.y);
    XI[4] = pk(v1.x, v2.z);
    XI[5] = pk(v1.y, v2.w);

    // ---------------- pre-net MLP (packed, weights in shared) ---------------
    u64 acc[NQ];
#pragma unroll
    for (int j = 0; j < NQ; ++j) acc[j] = lds64(&sb2d[j]);

#pragma unroll
    for (int k = 0; k < PRE; ++k) {
        const ulonglong2* wq = reinterpret_cast<const ulonglong2*>(&sW1d[k][0]);
        u64 h = lds64(&sW1d[k][6]);
        ulonglong2 p01 = wq[0];
        h = fma2(p01.x, XI[0], h);
        h = fma2(p01.y, XI[1], h);
        ulonglong2 p23 = wq[1];
        h = fma2(p23.x, XI[2], h);
        h = fma2(p23.y, XI[3], h);
        ulonglong2 p45 = wq[2];
        h = fma2(p45.x, XI[4], h);
        h = fma2(p45.y, XI[5], h);
        h = relu2(h);
        const ulonglong2* w2 = reinterpret_cast<const ulonglong2*>(&sW2d[k][0]);
        ulonglong2 a01 = w2[0];
        acc[0] = fma2(a01.x, h, acc[0]);
        acc[1] = fma2(a01.y, h, acc[1]);
        ulonglong2 a23 = w2[1];
        acc[2] = fma2(a23.x, h, acc[2]);
        acc[3] = fma2(a23.y, h, acc[3]);
        ulonglong2 a45 = w2[2];
        acc[4] = fma2(a45.x, h, acc[4]);
        acc[5] = fma2(a45.y, h, acc[5]);
    }

    // ---------------- angle embedding ---------------------------------------
    u64 ECP[NQ], ESP[NQ];
#pragma unroll
    for (int j = 0; j < NQ; ++j) {
        float a0, a1;
        upk(relu2(acc[j]), a0, a1);
        float s0, c0, s1c, c1;
        __sincosf(0.5f * a0, &s0, &c0);
        __sincosf(0.5f * a1, &s1c, &c1);
        ECP[j] = pk(c0, c1);
        ESP[j] = pk(s0, s1c);
    }

    u64 P[NS];
    P[0] = ECP[0];
    P[1] = ESP[0];
#pragma unroll
    for (int q = 1; q < NQ; ++q) {
        const int sz = 1 << q;
#pragma unroll
        for (int i = 0; i < NS; ++i) {
            if (i < sz) {
                P[i | sz] = mul2(P[i], ESP[q]);
                P[i]      = mul2(P[i], ECP[q]);
            }
        }
    }

    // ---------------- 4 layers: CNOT renames + tan RY (consts from cbank) ---
#pragma unroll
    for (int l = 0; l < NL; ++l) {
#pragma unroll
        for (int i = 0; i < NQ; ++i) {
            const int cb = 1 << i;
            const int tb = 1 << ((i + 1) % NQ);
#pragma unroll
            for (int idx = 0; idx < NS; ++idx) {
                if ((idx & cb) && !(idx & tb)) {
                    u64 tmp = P[idx];
                    P[idx] = P[idx | tb];
                    P[idx | tb] = tmp;
                }
            }
        }
#pragma unroll
        for (int i = 0; i < NQ; ++i) {
            const int g = l * NQ + i;
            const u64 Tt = cq.T[g];   // LDCU -> uniform register
            const u64 Nt = cq.N[g];
            const int qb = 1 << i;
#pragma unroll
            for (int base = 0; base < NS; ++base) {
                if (!(base & qb)) {
                    u64 A = P[base];
                    u64 B = P[base | qb];
                    P[base]      = fma2(Nt, B, A);
                    P[base | qb] = fma2(Tt, A, B);
                }
            }
        }
    }

    // ---------------- measurement (in place) --------------------------------
#pragma unroll
    for (int i = 0; i < NS; ++i) P[i] = mul2(P[i], P[i]);

    u64 F[NQ];
    {
        u64 e0a = pk(0.f, 0.f), e0b = pk(0.f, 0.f);
#pragma unroll
        for (int i = 0; i < 32; ++i) {
            u64 ev = P[2 * i], od = P[2 * i + 1];
            if (i & 1) e0b = add2(e0b, ev); else e0a = add2(e0a, ev);
            P[i] = add2(ev, od);
        }
        F[0] = add2(e0a, e0b);
    }
    {
        u64 e1a = pk(0.f, 0.f), e1b = pk(0.f, 0.f);
#pragma unroll
        for (int i = 0; i < 16; ++i) {
            u64 ev = P[2 * i], od = P[2 * i + 1];
            if (i & 1) e1b = add2(e1b, ev); else e1a = add2(e1a, ev);
            P[i] = add2(ev, od);
        }
        F[1] = add2(e1a, e1b);
    }
    {
        u64 e2 = pk(0.f, 0.f);
#pragma unroll
        for (int i = 0; i < 8; ++i) {
            u64 ev = P[2 * i], od = P[2 * i + 1];
            e2 = add2(e2, ev);
            P[i] = add2(ev, od);
        }
        F[2] = e2;
    }
    {
        u64 e3 = pk(0.f, 0.f);
#pragma unroll
        for (int i = 0; i < 4; ++i) {
            u64 ev = P[2 * i], od = P[2 * i + 1];
            e3 = add2(e3, ev);
            P[i] = add2(ev, od);
        }
        F[3] = e3;
    }
    F[4] = add2(P[0], P[2]);
    F[5] = add2(P[0], P[1]);

    // ---------------- heads (constants from cbank) ---------------------------
    u64 L[NA + 1];
#pragma unroll
    for (int r = 0; r < NA + 1; ++r) {
        u64 a = cq.Hb[r];
#pragma unroll
        for (int q = 0; q < NQ; ++q)
            a = fma2(cq.Hw[r][q], F[q], a);
        L[r] = a;
    }
    float l0[NA], l1[NA];
#pragma unroll
    for (int a = 0; a < NA; ++a) upk(L[a], l0[a], l1[a]);

    {
        float m = fmaxf(fmaxf(l0[0], l0[1]), fmaxf(l0[2], l0[3]));
        float e0 = __expf(l0[0] - m), e1 = __expf(l0[1] - m);
        float e2 = __expf(l0[2] - m), e3 = __expf(l0[3] - m);
        float inv = __fdividef(1.0f, e0 + e1 + e2 + e3);
        reinterpret_cast<float4*>(out_policy)[2 * t] =
            make_float4(e0 * inv, e1 * inv, e2 * inv, e3 * inv);
    }
    {
        float m = fmaxf(fmaxf(l1[0], l1[1]), fmaxf(l1[2], l1[3]));
        float e0 = __expf(l1[0] - m), e1 = __expf(l1[1] - m);
        float e2 = __expf(l1[2] - m), e3 = __expf(l1[3] - m);
        float inv = __fdividef(1.0f, e0 + e1 + e2 + e3);
        reinterpret_cast<float4*>(out_policy)[2 * t + 1] =
            make_float4(e0 * inv, e1 * inv, e2 * inv, e3 * inv);
    }

    float va, vb; upk(L[NA], va, vb);
    reinterpret_cast<float2*>(out_value)[t] = make_float2(va, vb);
}

extern "C" void kernel_launch(void* const* d_in, const int* in_sizes, int n_in,
                              void* d_out, int out_size) {
    const float* x  = (const float*)d_in[0];
    const float* W1 = (const float*)d_in[1];
    const float* b1 = (const float*)d_in[2];
    const float* W2 = (const float*)d_in[3];
    const float* b2 = (const float*)d_in[4];
    const float* qw = (const float*)d_in[5];
    const float* Wp = (const float*)d_in[6];
    const float* bp = (const float*)d_in[7];
    const float* Wv = (const float*)d_in[8];
    const float* bv = (const float*)d_in[9];

    const int B  = in_sizes[0] / NQ;
    const int NT = B / 2;
    float* out_policy = (float*)d_out;
    float* out_value  = (float*)d_out + (size_t)B * NA;

    build_consts<<<1, 32>>>(qw, Wp, bp, Wv, bv);

    void* stage_ptr = nullptr;
    cudaGetSymbolAddress(&stage_ptr, g_stage);
    cudaMemcpyToSymbolAsync(cq, stage_ptr, sizeof(QConst), 0,
                            cudaMemcpyDeviceToDevice, 0);

    const int threads = 128;
    const int blocks = (NT + threads - 1) / threads;
    qpolicy_kernel<<<blocks, threads>>>(x, W1, b1, W2, b2,
                                        out_policy, out_value, NT);
}

// round 9
// speedup vs baseline: 1.4661x; 1.0213x over previous
#include <cuda_runtime.h>
#include <math.h>

#define NQ 6
#define NL 4
#define NA 4
#define PRE 64
#define NS 64

typedef unsigned long long u64;

// ---- gate + head constants (uniform across all samples) --------------------
struct QConst {
    u64 T[NL * NQ];       // ( t,  t) per gate
    u64 N[NL * NQ];       // (-t, -t) per gate
    u64 Hw[NA + 1][NQ];   // (2*G2*w, dup)
    u64 Hb[NA + 1];       // (bias - G2*sumW*Tc, dup)
};
__constant__ QConst cq;

__device__ __forceinline__ u64 pk(float lo_, float hi_) {
    u64 r; asm("mov.b64 %0, {%1, %2};" : "=l"(r) : "f"(lo_), "f"(hi_)); return r;
}
__device__ __forceinline__ void upk(u64 v, float &lo_, float &hi_) {
    asm("mov.b64 {%0, %1}, %2;" : "=f"(lo_), "=f"(hi_) : "l"(v));
}
__device__ __forceinline__ u64 fma2(u64 a, u64 b, u64 c) {
    u64 d; asm("fma.rn.f32x2 %0, %1, %2, %3;" : "=l"(d) : "l"(a), "l"(b), "l"(c)); return d;
}
__device__ __forceinline__ u64 mul2(u64 a, u64 b) {
    u64 d; asm("mul.rn.f32x2 %0, %1, %2;" : "=l"(d) : "l"(a), "l"(b)); return d;
}
__device__ __forceinline__ u64 add2(u64 a, u64 b) {
    u64 d; asm("add.rn.f32x2 %0, %1, %2;" : "=l"(d) : "l"(a), "l"(b)); return d;
}
__device__ __forceinline__ u64 relu2(u64 v) {
    float a, b; upk(v, a, b);
    return pk(fmaxf(a, 0.0f), fmaxf(b, 0.0f));
}
__device__ __forceinline__ u64 lds64(const float2* p) {
    return *reinterpret_cast<const u64*>(p);
}

// ============================================================================
// Builder: writes gate/head constants DIRECTLY into cq's backing storage.
// Values depend only on fixed inputs -> deterministic across replays.
// ============================================================================
__global__ void build_consts(
    QConst* __restrict__ out,
    const float* __restrict__ qw,
    const float* __restrict__ Wp, const float* __restrict__ bp,
    const float* __restrict__ Wv, const float* __restrict__ bv)
{
    const int tid = threadIdx.x;   // 32 threads
    __shared__ float sc[NL * NQ], stt[NL * NQ];
    __shared__ float sG2, sTc;

    if (tid < NL * NQ) {
        float s, c;
        sincosf(0.5f * qw[tid], &s, &c);
        float t = s / c;
        sc[tid] = c;
        stt[tid] = t;
        out->T[tid] = pk(t, t);
        out->N[tid] = pk(-t, -t);
    }
    __syncthreads();
    if (tid == 0) {
        float g = 1.0f, T = 1.0f;
#pragma unroll
        for (int i = 0; i < NL * NQ; ++i) {
            g *= sc[i];
            T *= 1.0f + stt[i] * stt[i];
        }
        sG2 = g * g;
        sTc = T;
    }
    __syncthreads();
    if (tid < (NA + 1) * NQ) {
        int r = tid / NQ, q = tid % NQ;
        float w = (r < NA) ? Wp[r * NQ + q] : Wv[q];
        float v = 2.0f * sG2 * w;
        out->Hw[r][q] = pk(v, v);
    }
    if (tid < NA + 1) {
        const float* Wr = (tid < NA) ? (Wp + tid * NQ) : Wv;
        float bias = (tid < NA) ? bp[tid] : bv[0];
        float rs = 0.0f;
#pragma unroll
        for (int q = 0; q < NQ; ++q) rs += Wr[q];
        out->Hb[tid] = pk(bias - sG2 * rs * sTc, bias - sG2 * rs * sTc);
    }
}

// ============================================================================
// Main kernel: packed 2 samples/thread; 64-thread blocks for 14 warps/SM.
// ============================================================================
__global__ void __launch_bounds__(64) qpolicy_kernel(
    const float* __restrict__ x,
    const float* __restrict__ W1, const float* __restrict__ b1,
    const float* __restrict__ W2, const float* __restrict__ b2,
    float* __restrict__ out_policy, float* __restrict__ out_value,
    int NT)   // NT = B/2
{
    __shared__ __align__(16) float2 sW1d[PRE][8];   // [k][0..5]=W1 dup, [6]=b1 dup
    __shared__ __align__(16) float2 sW2d[PRE][6];   // [k][j]=W2[j][k] dup
    __shared__ __align__(16) float2 sb2d[NQ];

    const int tid = threadIdx.x;
    for (int i = tid; i < PRE * NQ; i += 64) {
        int k = i / NQ, q = i % NQ;
        float w = W1[i];
        sW1d[k][q] = make_float2(w, w);
        float w2 = W2[q * PRE + k];
        sW2d[k][q] = make_float2(w2, w2);
    }
    if (tid < PRE) { float v = b1[tid]; sW1d[tid][6] = make_float2(v, v); }
    if (tid < NQ)  { float v = b2[tid]; sb2d[tid] = make_float2(v, v); }
    __syncthreads();

    const int t = blockIdx.x * 64 + tid;
    if (t >= NT) return;

    // ---------------- load two samples --------------------------------------
    const float4* xr = reinterpret_cast<const float4*>(x + (size_t)t * 12);
    float4 v0 = xr[0], v1 = xr[1], v2 = xr[2];
    u64 XI[NQ];
    XI[0] = pk(v0.x, v1.z);
    XI[1] = pk(v0.y, v1.w);
    XI[2] = pk(v0.z, v2.x);
    XI[3] = pk(v0.w, v2.y);
    XI[4] = pk(v1.x, v2.z);
    XI[5] = pk(v1.y, v2.w);

    // ---------------- pre-net MLP (packed, weights in shared) ---------------
    u64 acc[NQ];
#pragma unroll
    for (int j = 0; j < NQ; ++j) acc[j] = lds64(&sb2d[j]);

#pragma unroll
    for (int k = 0; k < PRE; ++k) {
        const ulonglong2* wq = reinterpret_cast<const ulonglong2*>(&sW1d[k][0]);
        u64 h = lds64(&sW1d[k][6]);
        ulonglong2 p01 = wq[0];
        h = fma2(p01.x, XI[0], h);
        h = fma2(p01.y, XI[1], h);
        ulonglong2 p23 = wq[1];
        h = fma2(p23.x, XI[2], h);
        h = fma2(p23.y, XI[3], h);
        ulonglong2 p45 = wq[2];
        h = fma2(p45.x, XI[4], h);
        h = fma2(p45.y, XI[5], h);
        h = relu2(h);
        const ulonglong2* w2 = reinterpret_cast<const ulonglong2*>(&sW2d[k][0]);
        ulonglong2 a01 = w2[0];
        acc[0] = fma2(a01.x, h, acc[0]);
        acc[1] = fma2(a01.y, h, acc[1]);
        ulonglong2 a23 = w2[1];
        acc[2] = fma2(a23.x, h, acc[2]);
        acc[3] = fma2(a23.y, h, acc[3]);
        ulonglong2 a45 = w2[2];
        acc[4] = fma2(a45.x, h, acc[4]);
        acc[5] = fma2(a45.y, h, acc[5]);
    }

    // ---------------- angle embedding ---------------------------------------
    u64 ECP[NQ], ESP[NQ];
#pragma unroll
    for (int j = 0; j < NQ; ++j) {
        float a0, a1;
        upk(relu2(acc[j]), a0, a1);
        float s0, c0, s1c, c1;
        __sincosf(0.5f * a0, &s0, &c0);
        __sincosf(0.5f * a1, &s1c, &c1);
        ECP[j] = pk(c0, c1);
        ESP[j] = pk(s0, s1c);
    }

    u64 P[NS];
    P[0] = ECP[0];
    P[1] = ESP[0];
#pragma unroll
    for (int q = 1; q < NQ; ++q) {
        const int sz = 1 << q;
#pragma unroll
        for (int i = 0; i < NS; ++i) {
            if (i < sz) {
                P[i | sz] = mul2(P[i], ESP[q]);
                P[i]      = mul2(P[i], ECP[q]);
            }
        }
    }

    // ---------------- 4 layers: CNOT renames + tan RY (consts -> UR) --------
#pragma unroll
    for (int l = 0; l < NL; ++l) {
#pragma unroll
        for (int i = 0; i < NQ; ++i) {
            const int cb = 1 << i;
            const int tb = 1 << ((i + 1) % NQ);
#pragma unroll
            for (int idx = 0; idx < NS; ++idx) {
                if ((idx & cb) && !(idx & tb)) {
                    u64 tmp = P[idx];
                    P[idx] = P[idx | tb];
                    P[idx | tb] = tmp;
                }
            }
        }
#pragma unroll
        for (int i = 0; i < NQ; ++i) {
            const int g = l * NQ + i;
            const u64 Tt = cq.T[g];   // LDCU -> uniform register
            const u64 Nt = cq.N[g];
            const int qb = 1 << i;
#pragma unroll
            for (int base = 0; base < NS; ++base) {
                if (!(base & qb)) {
                    u64 A = P[base];
                    u64 B = P[base | qb];
                    P[base]      = fma2(Nt, B, A);
                    P[base | qb] = fma2(Tt, A, B);
                }
            }
        }
    }

    // ---------------- measurement (in place) --------------------------------
#pragma unroll
    for (int i = 0; i < NS; ++i) P[i] = mul2(P[i], P[i]);

    u64 F[NQ];
    {
        u64 e0a = P[0], e0b = P[2];
#pragma unroll
        for (int i = 0; i < 32; ++i) {
            u64 ev = P[2 * i], od = P[2 * i + 1];
            if (i >= 2) {
                if (i & 1) e0b = add2(e0b, ev); else e0a = add2(e0a, ev);
            }
            P[i] = add2(ev, od);
        }
        F[0] = add2(e0a, e0b);
    }
    {
        u64 e1a = P[0], e1b = P[2];
#pragma unroll
        for (int i = 0; i < 16; ++i) {
            u64 ev = P[2 * i], od = P[2 * i + 1];
            if (i >= 2) {
                if (i & 1) e1b = add2(e1b, ev); else e1a = add2(e1a, ev);
            }
            P[i] = add2(ev, od);
        }
        F[1] = add2(e1a, e1b);
    }
    {
        u64 e2 = P[0];
#pragma unroll
        for (int i = 0; i < 8; ++i) {
            u64 ev = P[2 * i], od = P[2 * i + 1];
            if (i >= 1) e2 = add2(e2, ev);
            P[i] = add2(ev, od);
        }
        F[2] = e2;
    }
    {
        u64 e3 = P[0];
#pragma unroll
        for (int i = 0; i < 4; ++i) {
            u64 ev = P[2 * i], od = P[2 * i + 1];
            if (i >= 1) e3 = add2(e3, ev);
            P[i] = add2(ev, od);
        }
        F[3] = e3;
    }
    F[4] = add2(P[0], P[2]);
    F[5] = add2(P[0], P[1]);

    // ---------------- heads (constants from cbank) ---------------------------
    u64 L[NA + 1];
#pragma unroll
    for (int r = 0; r < NA + 1; ++r) {
        u64 a = cq.Hb[r];
#pragma unroll
        for (int q = 0; q < NQ; ++q)
            a = fma2(cq.Hw[r][q], F[q], a);
        L[r] = a;
    }
    float l0[NA], l1[NA];
#pragma unroll
    for (int a = 0; a < NA; ++a) upk(L[a], l0[a], l1[a]);

    {
        float m = fmaxf(fmaxf(l0[0], l0[1]), fmaxf(l0[2], l0[3]));
        float e0 = __expf(l0[0] - m), e1 = __expf(l0[1] - m);
        float e2 = __expf(l0[2] - m), e3 = __expf(l0[3] - m);
        float inv = __fdividef(1.0f, e0 + e1 + e2 + e3);
        reinterpret_cast<float4*>(out_policy)[2 * t] =
            make_float4(e0 * inv, e1 * inv, e2 * inv, e3 * inv);
    }
    {
        float m = fmaxf(fmaxf(l1[0], l1[1]), fmaxf(l1[2], l1[3]));
        float e0 = __expf(l1[0] - m), e1 = __expf(l1[1] - m);
        float e2 = __expf(l1[2] - m), e3 = __expf(l1[3] - m);
        float inv = __fdividef(1.0f, e0 + e1 + e2 + e3);
        reinterpret_cast<float4*>(out_policy)[2 * t + 1] =
            make_float4(e0 * inv, e1 * inv, e2 * inv, e3 * inv);
    }

    float va, vb; upk(L[NA], va, vb);
    reinterpret_cast<float2*>(out_value)[t] = make_float2(va, vb);
}

extern "C" void kernel_launch(void* const* d_in, const int* in_sizes, int n_in,
                              void* d_out, int out_size) {
    const float* x  = (const float*)d_in[0];
    const float* W1 = (const float*)d_in[1];
    const float* b1 = (const float*)d_in[2];
    const float* W2 = (const float*)d_in[3];
    const float* b2 = (const float*)d_in[4];
    const float* qw = (const float*)d_in[5];
    const float* Wp = (const float*)d_in[6];
    const float* bp = (const float*)d_in[7];
    const float* Wv = (const float*)d_in[8];
    const float* bv = (const float*)d_in[9];

    const int B  = in_sizes[0] / NQ;
    const int NT = B / 2;
    float* out_policy = (float*)d_out;
    float* out_value  = (float*)d_out + (size_t)B * NA;

    // Write constants directly into cq's device backing store (no memcpy node).
    void* cq_ptr = nullptr;
    cudaGetSymbolAddress(&cq_ptr, cq);
    build_consts<<<1, 32>>>((QConst*)cq_ptr, qw, Wp, bp, Wv, bv);

    const int threads = 64;
    const int blocks = (NT + threads - 1) / threads;
    qpolicy_kernel<<<blocks, threads>>>(x, W1, b1, W2, b2,
                                        out_policy, out_value, NT);
}

// round 10
// speedup vs baseline: 1.5102x; 1.0301x over previous
#include <cuda_runtime.h>
#include <math.h>

#define NQ 6
#define NL 4
#define NA 4
#define PRE 64
#define NS 64

typedef unsigned long long u64;

// ---- ALL warp-uniform constants live in cbank (LDCU -> UR operands) --------
struct QConst {
    u64 W1p[PRE][NQ];     // (w,w) dup pairs, W1[k][q]
    u64 B1[PRE];          // (b1,b1)
    u64 W2p[PRE][NQ];     // (w,w) dup pairs, W2[j][k] stored [k][j]
    u64 B2[NQ];           // (b2,b2)
    u64 T[NL * NQ];       // ( t,  t) per gate
    u64 N[NL * NQ];       // (-t, -t) per gate
    u64 Hw[NA + 1][NQ];   // (2*G2*w, dup)
    u64 Hb[NA + 1];       // (bias - G2*sumW*Tc, dup)
};
__constant__ QConst cq;

__device__ __forceinline__ u64 pk(float lo_, float hi_) {
    u64 r; asm("mov.b64 %0, {%1, %2};" : "=l"(r) : "f"(lo_), "f"(hi_)); return r;
}
__device__ __forceinline__ void upk(u64 v, float &lo_, float &hi_) {
    asm("mov.b64 {%0, %1}, %2;" : "=f"(lo_), "=f"(hi_) : "l"(v));
}
__device__ __forceinline__ u64 fma2(u64 a, u64 b, u64 c) {
    u64 d; asm("fma.rn.f32x2 %0, %1, %2, %3;" : "=l"(d) : "l"(a), "l"(b), "l"(c)); return d;
}
__device__ __forceinline__ u64 mul2(u64 a, u64 b) {
    u64 d; asm("mul.rn.f32x2 %0, %1, %2;" : "=l"(d) : "l"(a), "l"(b)); return d;
}
__device__ __forceinline__ u64 add2(u64 a, u64 b) {
    u64 d; asm("add.rn.f32x2 %0, %1, %2;" : "=l"(d) : "l"(a), "l"(b)); return d;
}
__device__ __forceinline__ u64 relu2(u64 v) {
    float a, b; upk(v, a, b);
    return pk(fmaxf(a, 0.0f), fmaxf(b, 0.0f));
}

// ============================================================================
// Builder: writes ALL constants directly into cq's device backing storage.
// ============================================================================
__global__ void __launch_bounds__(256) build_consts(
    QConst* __restrict__ out,
    const float* __restrict__ qw,
    const float* __restrict__ W1, const float* __restrict__ b1,
    const float* __restrict__ W2, const float* __restrict__ b2,
    const float* __restrict__ Wp, const float* __restrict__ bp,
    const float* __restrict__ Wv, const float* __restrict__ bv)
{
    const int tid = threadIdx.x;
    __shared__ float sc[NL * NQ], stt[NL * NQ];
    __shared__ float sG2, sTc;

    // MLP weights as dup pairs
    for (int i = tid; i < PRE * NQ; i += 256) {
        int k = i / NQ, q = i % NQ;
        float w = W1[i];
        out->W1p[k][q] = pk(w, w);
        float w2 = W2[q * PRE + k];
        out->W2p[k][q] = pk(w2, w2);
    }
    if (tid < PRE) { float v = b1[tid]; out->B1[tid] = pk(v, v); }
    if (tid < NQ)  { float v = b2[tid]; out->B2[tid] = pk(v, v); }

    if (tid < NL * NQ) {
        float s, c;
        sincosf(0.5f * qw[tid], &s, &c);
        float t = s / c;
        sc[tid] = c;
        stt[tid] = t;
        out->T[tid] = pk(t, t);
        out->N[tid] = pk(-t, -t);
    }
    __syncthreads();
    if (tid == 0) {
        float g = 1.0f, T = 1.0f;
#pragma unroll
        for (int i = 0; i < NL * NQ; ++i) {
            g *= sc[i];
            T *= 1.0f + stt[i] * stt[i];
        }
        sG2 = g * g;
        sTc = T;
    }
    __syncthreads();
    if (tid < (NA + 1) * NQ) {
        int r = tid / NQ, q = tid % NQ;
        float w = (r < NA) ? Wp[r * NQ + q] : Wv[q];
        float v = 2.0f * sG2 * w;
        out->Hw[r][q] = pk(v, v);
    }
    if (tid < NA + 1) {
        const float* Wr = (tid < NA) ? (Wp + tid * NQ) : Wv;
        float bias = (tid < NA) ? bp[tid] : bv[0];
        float rs = 0.0f;
#pragma unroll
        for (int q = 0; q < NQ; ++q) rs += Wr[q];
        float v = bias - sG2 * rs * sTc;
        out->Hb[tid] = pk(v, v);
    }
}

// ============================================================================
// Main kernel: 2 samples/thread (f32x2); ALL uniform operands from cbank/UR.
// No shared memory, no block-level sync.
// ============================================================================
__global__ void __launch_bounds__(64) qpolicy_kernel(
    const float* __restrict__ x,
    float* __restrict__ out_policy, float* __restrict__ out_value,
    int NT)   // NT = B/2
{
    const int t = blockIdx.x * 64 + threadIdx.x;
    if (t >= NT) return;

    // ---------------- load two samples --------------------------------------
    const float4* xr = reinterpret_cast<const float4*>(x + (size_t)t * 12);
    float4 v0 = xr[0], v1 = xr[1], v2 = xr[2];
    u64 XI[NQ];
    XI[0] = pk(v0.x, v1.z);
    XI[1] = pk(v0.y, v1.w);
    XI[2] = pk(v0.z, v2.x);
    XI[3] = pk(v0.w, v2.y);
    XI[4] = pk(v1.x, v2.z);
    XI[5] = pk(v1.y, v2.w);

    // ---------------- pre-net MLP (all weights via cbank -> UR) -------------
    u64 acc[NQ];
#pragma unroll
    for (int j = 0; j < NQ; ++j) acc[j] = cq.B2[j];

#pragma unroll
    for (int k = 0; k < PRE; ++k) {
        u64 h = cq.B1[k];
        h = fma2(cq.W1p[k][0], XI[0], h);
        h = fma2(cq.W1p[k][1], XI[1], h);
        h = fma2(cq.W1p[k][2], XI[2], h);
        h = fma2(cq.W1p[k][3], XI[3], h);
        h = fma2(cq.W1p[k][4], XI[4], h);
        h = fma2(cq.W1p[k][5], XI[5], h);
        h = relu2(h);
        acc[0] = fma2(cq.W2p[k][0], h, acc[0]);
        acc[1] = fma2(cq.W2p[k][1], h, acc[1]);
        acc[2] = fma2(cq.W2p[k][2], h, acc[2]);
        acc[3] = fma2(cq.W2p[k][3], h, acc[3]);
        acc[4] = fma2(cq.W2p[k][4], h, acc[4]);
        acc[5] = fma2(cq.W2p[k][5], h, acc[5]);
    }

    // ---------------- angle embedding ---------------------------------------
    u64 ECP[NQ], ESP[NQ];
#pragma unroll
    for (int j = 0; j < NQ; ++j) {
        float a0, a1;
        upk(relu2(acc[j]), a0, a1);
        float s0, c0, s1c, c1;
        __sincosf(0.5f * a0, &s0, &c0);
        __sincosf(0.5f * a1, &s1c, &c1);
        ECP[j] = pk(c0, c1);
        ESP[j] = pk(s0, s1c);
    }

    u64 P[NS];
    P[0] = ECP[0];
    P[1] = ESP[0];
#pragma unroll
    for (int q = 1; q < NQ; ++q) {
        const int sz = 1 << q;
#pragma unroll
        for (int i = 0; i < NS; ++i) {
            if (i < sz) {
                P[i | sz] = mul2(P[i], ESP[q]);
                P[i]      = mul2(P[i], ECP[q]);
            }
        }
    }

    // ---------------- 4 layers: CNOT renames + tan RY (consts -> UR) --------
#pragma unroll
    for (int l = 0; l < NL; ++l) {
#pragma unroll
        for (int i = 0; i < NQ; ++i) {
            const int cb = 1 << i;
            const int tb = 1 << ((i + 1) % NQ);
#pragma unroll
            for (int idx = 0; idx < NS; ++idx) {
                if ((idx & cb) && !(idx & tb)) {
                    u64 tmp = P[idx];
                    P[idx] = P[idx | tb];
                    P[idx | tb] = tmp;
                }
            }
        }
#pragma unroll
        for (int i = 0; i < NQ; ++i) {
            const int g = l * NQ + i;
            const u64 Tt = cq.T[g];
            const u64 Nt = cq.N[g];
            const int qb = 1 << i;
#pragma unroll
            for (int base = 0; base < NS; ++base) {
                if (!(base & qb)) {
                    u64 A = P[base];
                    u64 B = P[base | qb];
                    P[base]      = fma2(Nt, B, A);
                    P[base | qb] = fma2(Tt, A, B);
                }
            }
        }
    }

    // ---------------- measurement (in place) --------------------------------
#pragma unroll
    for (int i = 0; i < NS; ++i) P[i] = mul2(P[i], P[i]);

    u64 F[NQ];
    {
        u64 e0a = P[0], e0b = P[2];
#pragma unroll
        for (int i = 0; i < 32; ++i) {
            u64 ev = P[2 * i], od = P[2 * i + 1];
            if (i >= 2) {
                if (i & 1) e0b = add2(e0b, ev); else e0a = add2(e0a, ev);
            }
            P[i] = add2(ev, od);
        }
        F[0] = add2(e0a, e0b);
    }
    {
        u64 e1a = P[0], e1b = P[2];
#pragma unroll
        for (int i = 0; i < 16; ++i) {
            u64 ev = P[2 * i], od = P[2 * i + 1];
            if (i >= 2) {
                if (i & 1) e1b = add2(e1b, ev); else e1a = add2(e1a, ev);
            }
            P[i] = add2(ev, od);
        }
        F[1] = add2(e1a, e1b);
    }
    {
        u64 e2 = P[0];
#pragma unroll
        for (int i = 0; i < 8; ++i) {
            u64 ev = P[2 * i], od = P[2 * i + 1];
            if (i >= 1) e2 = add2(e2, ev);
            P[i] = add2(ev, od);
        }
        F[2] = e2;
    }
    {
        u64 e3 = P[0];
#pragma unroll
        for (int i = 0; i < 4; ++i) {
            u64 ev = P[2 * i], od = P[2 * i + 1];
            if (i >= 1) e3 = add2(e3, ev);
            P[i] = add2(ev, od);
        }
        F[3] = e3;
    }
    F[4] = add2(P[0], P[2]);
    F[5] = add2(P[0], P[1]);

    // ---------------- heads (constants -> UR) -------------------------------
    u64 L[NA + 1];
#pragma unroll
    for (int r = 0; r < NA + 1; ++r) {
        u64 a = cq.Hb[r];
#pragma unroll
        for (int q = 0; q < NQ; ++q)
            a = fma2(cq.Hw[r][q], F[q], a);
        L[r] = a;
    }
    float l0[NA], l1[NA];
#pragma unroll
    for (int a = 0; a < NA; ++a) upk(L[a], l0[a], l1[a]);

    {
        float m = fmaxf(fmaxf(l0[0], l0[1]), fmaxf(l0[2], l0[3]));
        float e0 = __expf(l0[0] - m), e1 = __expf(l0[1] - m);
        float e2 = __expf(l0[2] - m), e3 = __expf(l0[3] - m);
        float inv = __fdividef(1.0f, e0 + e1 + e2 + e3);
        reinterpret_cast<float4*>(out_policy)[2 * t] =
            make_float4(e0 * inv, e1 * inv, e2 * inv, e3 * inv);
    }
    {
        float m = fmaxf(fmaxf(l1[0], l1[1]), fmaxf(l1[2], l1[3]));
        float e0 = __expf(l1[0] - m), e1 = __expf(l1[1] - m);
        float e2 = __expf(l1[2] - m), e3 = __expf(l1[3] - m);
        float inv = __fdividef(1.0f, e0 + e1 + e2 + e3);
        reinterpret_cast<float4*>(out_policy)[2 * t + 1] =
            make_float4(e0 * inv, e1 * inv, e2 * inv, e3 * inv);
    }

    float va, vb; upk(L[NA], va, vb);
    reinterpret_cast<float2*>(out_value)[t] = make_float2(va, vb);
}

extern "C" void kernel_launch(void* const* d_in, const int* in_sizes, int n_in,
                              void* d_out, int out_size) {
    const float* x  = (const float*)d_in[0];
    const float* W1 = (const float*)d_in[1];
    const float* b1 = (const float*)d_in[2];
    const float* W2 = (const float*)d_in[3];
    const float* b2 = (const float*)d_in[4];
    const float* qw = (const float*)d_in[5];
    const float* Wp = (const float*)d_in[6];
    const float* bp = (const float*)d_in[7];
    const float* Wv = (const float*)d_in[8];
    const float* bv = (const float*)d_in[9];

    const int B  = in_sizes[0] / NQ;
    const int NT = B / 2;
    float* out_policy = (float*)d_out;
    float* out_value  = (float*)d_out + (size_t)B * NA;

    void* cq_ptr = nullptr;
    cudaGetSymbolAddress(&cq_ptr, cq);
    build_consts<<<1, 256>>>((QConst*)cq_ptr, qw, W1, b1, W2, b2, Wp, bp, Wv, bv);

    const int threads = 64;
    const int blocks = (NT + threads - 1) / threads;
    qpolicy_kernel<<<blocks, threads>>>(x, out_policy, out_value, NT);
}